// round 14
// baseline (speedup 1.0000x reference)
#include <cuda_runtime.h>
#include <math.h>

#define Hn   1024
#define En   1024
#define Tn   4096
#define Vn   50257
#define INPn 2049
#define VT   1024         // v-tile width (4KB per row-visit) — R10 optimum
#define NT   50           // ceil(Vn/VT)
#define HC   32           // rows per h-chunk
#define NC   (Hn/HC)      // 32 h-chunks

// ---- scratch (no allocations allowed; every buffer restores its own
//      initial state each replay, so no init kernel is needed) ----
__device__ float g_att[En];          // column sums of hiddens (zeroed by gates winner)
__device__ float g_h[Hn];            // LSTM output h (overwritten)
__device__ float g_part[NC * Vn];    // per-h-chunk partial logits (overwritten)
__device__ float g_exp[Vn];          // exp(logits) (overwritten)
__device__ float g_tsum[NT];         // per-v-tile exp sums (overwritten)
__device__ int   g_cnt[NT];          // v-tile arrival counters (self-resetting)
__device__ int   g_gcnt;             // gates arrival counter (self-resetting)

struct GateParams {
    const float* Wi[4];
    const float* Wh[4];
    const float* bi[4];
    const float* bh[4];
};

// Column sum of hiddens [T, E] (softmax over size-1 axis == all ones; the
// sigmoid scores are dead code). Relies on g_att == 0 at entry (invariant).
__global__ void k_colsum(const float* __restrict__ hid) {
    const float4* h4 = (const float4*)hid;       // [Tn][256] float4
    int t0 = blockIdx.x * 16;                    // 256 blocks x 16 rows
    float4 a = make_float4(0.f, 0.f, 0.f, 0.f);
    #pragma unroll
    for (int t = 0; t < 16; t++) {
        float4 v = __ldg(&h4[(size_t)(t0 + t) * 256 + threadIdx.x]);
        a.x += v.x; a.y += v.y; a.z += v.z; a.w += v.w;
    }
    int e = threadIdx.x * 4;
    atomicAdd(&g_att[e + 0], a.x);
    atomicAdd(&g_att[e + 1], a.y);
    atomicAdd(&g_att[e + 2], a.z);
    atomicAdd(&g_att[e + 3], a.w);
}

// Block b: rows {2b, 2b+1}. 8 warps = 4 gates x 2 rows; each warp streams its
// WHOLE Wi row (8KB) + Wh row (4KB) contiguously (page-economy pattern).
// Last-arrival block re-zeros g_att and resets the counter (replay invariant).
__global__ void k_gates(GateParams gp,
                        const float* __restrict__ sen,
                        const float* __restrict__ curh,
                        const float* __restrict__ curc,
                        const int*   __restrict__ pos) {
    __shared__ float sx[INPn];
    __shared__ float shh[Hn];
    __shared__ float sp[8];
    __shared__ int   sdone;
    int tid  = threadIdx.x;
    int wid  = tid >> 5;
    int lane = tid & 31;
    int gate = wid >> 1;
    int prty = wid & 1;
    int r    = blockIdx.x * 2 + prty;

    // pos_index dtype-defensive read
    int ib = __ldg(pos);
    float posv = ((unsigned)ib < (1u << 20)) ? (float)ib : __int_as_float(ib);

    for (int i = tid; i < INPn; i += 256)
        sx[i] = (i < En) ? __ldg(&sen[i]) : (i < En + Hn) ? g_att[i - En] : posv;
    for (int i = tid; i < Hn; i += 256)
        shh[i] = __ldg(&curh[i]);
    __syncthreads();

    const float* Wi = gp.Wi[gate] + (size_t)r * INPn;
    const float* Wh = gp.Wh[gate] + (size_t)r * Hn;

    float acc = 0.f;
    #pragma unroll 8
    for (int c = lane; c < INPn; c += 32)
        acc += __ldcs(&Wi[c]) * sx[c];
    #pragma unroll 8
    for (int c = lane; c < Hn; c += 32)
        acc += __ldcs(&Wh[c]) * shh[c];

    #pragma unroll
    for (int o = 16; o; o >>= 1)
        acc += __shfl_down_sync(0xffffffffu, acc, o);
    if (lane == 0) sp[wid] = acc;
    __syncthreads();

    if (tid < 2) {       // tid = row parity
        int rr = blockIdx.x * 2 + tid;
        float yi = sp[0 + tid] + __ldg(&gp.bi[0][rr]) + __ldg(&gp.bh[0][rr]);
        float yf = sp[2 + tid] + __ldg(&gp.bi[1][rr]) + __ldg(&gp.bh[1][rr]);
        float yg = sp[4 + tid] + __ldg(&gp.bi[2][rr]) + __ldg(&gp.bh[2][rr]);
        float yo = sp[6 + tid] + __ldg(&gp.bi[3][rr]) + __ldg(&gp.bh[3][rr]);
        float i = 1.f / (1.f + expf(-yi));
        float f = 1.f / (1.f + expf(-yf));
        float g = tanhf(yg);
        float o = 1.f / (1.f + expf(-yo));
        float c = f * __ldg(&curc[rr]) + i * g;
        g_h[rr] = o * tanhf(c);
    }

    // replay-invariant cleanup: last block (all g_att reads are done) zeroes
    // g_att for the NEXT replay's colsum and resets the counter.
    if (tid == 0) {
        __threadfence();
        sdone = (atomicAdd(&g_gcnt, 1) == (int)gridDim.x - 1);
    }
    __syncthreads();
    if (sdone) {
        for (int i = tid; i < En; i += 256) g_att[i] = 0.f;
        __threadfence();
        if (tid == 0) g_gcnt = 0;
    }
}

// Partial logits with 4KB-contiguous row-visits (R10 optimum structure).
// Grid (NT=50, NC=32): x = 1024-col v-tile, y = 32-row h-chunk. Warp owns
// 4 rows x 1024 cols (32 accumulators). R14 A/B: __ldg (default caching)
// instead of __ldcs — attributable via this kernel's DRAM% alone.
__global__ void __launch_bounds__(256, 4) k_logits(const float* __restrict__ dout) {
    __shared__ float sh[HC];
    __shared__ float red[8][VT];     // 32KB
    __shared__ float swsum[8];
    __shared__ int   slast;
    int tid  = threadIdx.x;
    int wid  = tid >> 5;
    int lane = tid & 31;
    int v0   = blockIdx.x * VT;
    int r0   = blockIdx.y * HC;

    if (tid < HC) sh[tid] = g_h[r0 + tid];
    __syncthreads();

    float a[32];
    #pragma unroll
    for (int k = 0; k < 32; k++) a[k] = 0.f;

    const float* rbase = dout + (size_t)(r0 + wid * 4) * Vn + v0 + lane;

    if (v0 + VT <= Vn) {
        #pragma unroll 1
        for (int rr = 0; rr < 4; rr++) {
            float hv = sh[wid * 4 + rr];
            const float* p = rbase + (size_t)rr * Vn;
            #pragma unroll
            for (int kb = 0; kb < 32; kb += 8) {
                float x0 = __ldg(p + 32 * (kb + 0));
                float x1 = __ldg(p + 32 * (kb + 1));
                float x2 = __ldg(p + 32 * (kb + 2));
                float x3 = __ldg(p + 32 * (kb + 3));
                float x4 = __ldg(p + 32 * (kb + 4));
                float x5 = __ldg(p + 32 * (kb + 5));
                float x6 = __ldg(p + 32 * (kb + 6));
                float x7 = __ldg(p + 32 * (kb + 7));
                a[kb + 0] = fmaf(hv, x0, a[kb + 0]);
                a[kb + 1] = fmaf(hv, x1, a[kb + 1]);
                a[kb + 2] = fmaf(hv, x2, a[kb + 2]);
                a[kb + 3] = fmaf(hv, x3, a[kb + 3]);
                a[kb + 4] = fmaf(hv, x4, a[kb + 4]);
                a[kb + 5] = fmaf(hv, x5, a[kb + 5]);
                a[kb + 6] = fmaf(hv, x6, a[kb + 6]);
                a[kb + 7] = fmaf(hv, x7, a[kb + 7]);
            }
        }
    } else {
        // tail v-tile (32 of 1600 blocks): guarded loads
        #pragma unroll 1
        for (int rr = 0; rr < 4; rr++) {
            float hv = sh[wid * 4 + rr];
            const float* p = rbase + (size_t)rr * Vn;
            #pragma unroll 4
            for (int k = 0; k < 32; k++)
                if (v0 + lane + 32 * k < Vn)
                    a[k] = fmaf(hv, __ldg(p + 32 * k), a[k]);
        }
    }

    #pragma unroll
    for (int k = 0; k < 32; k++)
        red[wid][lane + 32 * k] = a[k];
    __syncthreads();

    // 256 threads x 4 cols: reduce 8 warps, store partial strip
    #pragma unroll
    for (int j = 0; j < 4; j++) {
        int c = tid + 256 * j;
        float s = 0.f;
        #pragma unroll
        for (int w = 0; w < 8; w++) s += red[w][c];
        int v = v0 + c;
        if (v < Vn) g_part[(size_t)blockIdx.y * Vn + v] = s;
    }
    __syncthreads();

    // last-arrival fusion: the NC-th block for this v-tile finishes the
    // softmax numerator (deterministic fixed-order sum of the partials),
    // writes the per-tile exp sum, and resets the counter for the next replay.
    if (tid == 0) {
        __threadfence();
        slast = (atomicAdd(&g_cnt[blockIdx.x], 1) == NC - 1);
    }
    __syncthreads();
    if (slast) {
        __threadfence();   // acquire: order g_part reads after counter observe
        float esum = 0.f;
        #pragma unroll
        for (int j = 0; j < 4; j++) {
            int v = v0 + tid + 256 * j;
            if (v < Vn) {
                float l = 0.f;
                #pragma unroll 8
                for (int c = 0; c < NC; c++) l += g_part[(size_t)c * Vn + v];
                float e = expf(l);     // |logit| small; max-subtraction unnecessary
                g_exp[v] = e;
                esum += e;
            }
        }
        #pragma unroll
        for (int o = 16; o; o >>= 1)
            esum += __shfl_down_sync(0xffffffffu, esum, o);
        if (lane == 0) swsum[wid] = esum;
        __syncthreads();
        if (tid == 0) {
            float s = 0.f;
            #pragma unroll
            for (int w = 0; w < 8; w++) s += swsum[w];
            g_tsum[blockIdx.x] = s;
            g_cnt[blockIdx.x] = 0;     // replay invariant
        }
    }
}

// Normalize: denominator computed by warp 0 in PARALLEL (2 loads/lane + warp
// reduce), not a 50-deep serial chain.
__global__ void k_norm(float* __restrict__ out) {
    __shared__ float sden;
    int tid = threadIdx.x;
    if (tid < 32) {
        float s = (tid < NT) ? g_tsum[tid] : 0.f;
        if (tid + 32 < NT) s += g_tsum[tid + 32];
        #pragma unroll
        for (int o = 16; o; o >>= 1)
            s += __shfl_down_sync(0xffffffffu, s, o);
        if (tid == 0) sden = 1.f / s;
    }
    __syncthreads();
    int v = blockIdx.x * blockDim.x + tid;
    if (v < Vn) out[v] = g_exp[v] * sden;
}

extern "C" void kernel_launch(void* const* d_in, const int* in_sizes, int n_in,
                              void* d_out, int out_size) {
    const float* sen  = (const float*)d_in[0];
    const float* hid  = (const float*)d_in[1];
    const float* dout = (const float*)d_in[2];
    GateParams gp;
    for (int g = 0; g < 4; g++) {
        gp.Wi[g] = (const float*)d_in[3 + 4 * g];
        gp.Wh[g] = (const float*)d_in[4 + 4 * g];
        gp.bi[g] = (const float*)d_in[5 + 4 * g];
        gp.bh[g] = (const float*)d_in[6 + 4 * g];
    }
    const float* curh = (const float*)d_in[19];
    const float* curc = (const float*)d_in[20];
    const int*   pos  = (const int*)d_in[21];
    float* out = (float*)d_out;

    k_colsum<<<Tn / 16, 256>>>(hid);
    k_gates<<<Hn / 2, 256>>>(gp, sen, curh, curc, pos);
    k_logits<<<dim3(NT, NC), 256>>>(dout);
    k_norm<<<(Vn + 255) / 256, 256>>>(out);
}

// round 15
// speedup vs baseline: 1.1287x; 1.1287x over previous
#include <cuda_runtime.h>
#include <math.h>

#define Hn   1024
#define En   1024
#define Tn   4096
#define Vn   50257
#define INPn 2049
#define VT   1024         // v-tile width (4KB per row-visit) — R10 optimum
#define NT   50           // ceil(Vn/VT)
#define HC   32           // rows per h-chunk
#define NC   (Hn/HC)      // 32 h-chunks

// ---- scratch (no allocations allowed; every buffer restores its own
//      initial state each replay, so no init kernel is needed) ----
__device__ float g_att[En];          // column sums of hiddens (zeroed by gates winner)
__device__ float g_h[Hn];            // LSTM output h (overwritten)
__device__ float g_part[NC * Vn];    // per-h-chunk partial logits (overwritten)
__device__ float g_exp[Vn];          // exp(logits) (overwritten)
__device__ float g_tsum[NT];         // per-v-tile exp sums (overwritten)
__device__ int   g_cnt[NT];          // v-tile arrival counters (self-resetting)
__device__ int   g_gcnt;             // gates arrival counter (self-resetting)

struct GateParams {
    const float* Wi[4];
    const float* Wh[4];
    const float* bi[4];
    const float* bh[4];
};

// Column sum of hiddens [T, E] (softmax over size-1 axis == all ones; the
// sigmoid scores are dead code). Relies on g_att == 0 at entry (invariant).
__global__ void k_colsum(const float* __restrict__ hid) {
    const float4* h4 = (const float4*)hid;       // [Tn][256] float4
    int t0 = blockIdx.x * 16;                    // 256 blocks x 16 rows
    float4 a = make_float4(0.f, 0.f, 0.f, 0.f);
    #pragma unroll
    for (int t = 0; t < 16; t++) {
        float4 v = __ldg(&h4[(size_t)(t0 + t) * 256 + threadIdx.x]);
        a.x += v.x; a.y += v.y; a.z += v.z; a.w += v.w;
    }
    int e = threadIdx.x * 4;
    atomicAdd(&g_att[e + 0], a.x);
    atomicAdd(&g_att[e + 1], a.y);
    atomicAdd(&g_att[e + 2], a.z);
    atomicAdd(&g_att[e + 3], a.w);
}

// Block b: rows {2b, 2b+1}. 8 warps = 4 gates x 2 rows; each warp streams its
// WHOLE Wi row (8KB, scalar: odd stride) + Wh row (4KB, float4: aligned)
// contiguously. Last-arrival block re-zeros g_att (replay invariant).
__global__ void k_gates(GateParams gp,
                        const float* __restrict__ sen,
                        const float* __restrict__ curh,
                        const float* __restrict__ curc,
                        const int*   __restrict__ pos) {
    __shared__ float sx[INPn];
    __shared__ float shh[Hn];
    __shared__ float sp[8];
    __shared__ int   sdone;
    int tid  = threadIdx.x;
    int wid  = tid >> 5;
    int lane = tid & 31;
    int gate = wid >> 1;
    int prty = wid & 1;
    int r    = blockIdx.x * 2 + prty;

    // pos_index dtype-defensive read
    int ib = __ldg(pos);
    float posv = ((unsigned)ib < (1u << 20)) ? (float)ib : __int_as_float(ib);

    for (int i = tid; i < INPn; i += 256)
        sx[i] = (i < En) ? __ldg(&sen[i]) : (i < En + Hn) ? g_att[i - En] : posv;
    for (int i = tid; i < Hn; i += 256)
        shh[i] = __ldg(&curh[i]);
    __syncthreads();

    const float*  Wi  = gp.Wi[gate] + (size_t)r * INPn;
    const float4* Wh4 = (const float4*)(gp.Wh[gate] + (size_t)r * Hn); // 4KB rows

    float acc = 0.f;
    #pragma unroll 8
    for (int c = lane; c < INPn; c += 32)
        acc += __ldcs(&Wi[c]) * sx[c];
    #pragma unroll 4
    for (int c4 = lane; c4 < Hn / 4; c4 += 32) {
        float4 w = __ldcs(&Wh4[c4]);
        int c = c4 * 4;
        acc += w.x * shh[c] + w.y * shh[c + 1] + w.z * shh[c + 2] + w.w * shh[c + 3];
    }

    #pragma unroll
    for (int o = 16; o; o >>= 1)
        acc += __shfl_down_sync(0xffffffffu, acc, o);
    if (lane == 0) sp[wid] = acc;
    __syncthreads();

    if (tid < 2) {       // tid = row parity
        int rr = blockIdx.x * 2 + tid;
        float yi = sp[0 + tid] + __ldg(&gp.bi[0][rr]) + __ldg(&gp.bh[0][rr]);
        float yf = sp[2 + tid] + __ldg(&gp.bi[1][rr]) + __ldg(&gp.bh[1][rr]);
        float yg = sp[4 + tid] + __ldg(&gp.bi[2][rr]) + __ldg(&gp.bh[2][rr]);
        float yo = sp[6 + tid] + __ldg(&gp.bi[3][rr]) + __ldg(&gp.bh[3][rr]);
        float i = 1.f / (1.f + expf(-yi));
        float f = 1.f / (1.f + expf(-yf));
        float g = tanhf(yg);
        float o = 1.f / (1.f + expf(-yo));
        float c = f * __ldg(&curc[rr]) + i * g;
        g_h[rr] = o * tanhf(c);
    }

    // replay-invariant cleanup: last block (all g_att reads are done) zeroes
    // g_att for the NEXT replay's colsum and resets the counter.
    if (tid == 0) {
        __threadfence();
        sdone = (atomicAdd(&g_gcnt, 1) == (int)gridDim.x - 1);
    }
    __syncthreads();
    if (sdone) {
        for (int i = tid; i < En; i += 256) g_att[i] = 0.f;
        __threadfence();
        if (tid == 0) g_gcnt = 0;
    }
}

// Partial logits with 4KB-contiguous row-visits, __ldcs streaming loads
// (R13 known-good body: .cs is worth ~10us vs default — R14 A/B).
// Grid (NT=50, NC=32): x = 1024-col v-tile, y = 32-row h-chunk.
__global__ void __launch_bounds__(256, 4) k_logits(const float* __restrict__ dout) {
    __shared__ float sh[HC];
    __shared__ float red[8][VT];     // 32KB
    __shared__ float swsum[8];
    __shared__ int   slast;
    int tid  = threadIdx.x;
    int wid  = tid >> 5;
    int lane = tid & 31;
    int v0   = blockIdx.x * VT;
    int r0   = blockIdx.y * HC;

    if (tid < HC) sh[tid] = g_h[r0 + tid];
    __syncthreads();

    float a[32];
    #pragma unroll
    for (int k = 0; k < 32; k++) a[k] = 0.f;

    const float* rbase = dout + (size_t)(r0 + wid * 4) * Vn + v0 + lane;

    if (v0 + VT <= Vn) {
        #pragma unroll 1
        for (int rr = 0; rr < 4; rr++) {
            float hv = sh[wid * 4 + rr];
            const float* p = rbase + (size_t)rr * Vn;
            #pragma unroll
            for (int kb = 0; kb < 32; kb += 8) {
                float x0 = __ldcs(p + 32 * (kb + 0));
                float x1 = __ldcs(p + 32 * (kb + 1));
                float x2 = __ldcs(p + 32 * (kb + 2));
                float x3 = __ldcs(p + 32 * (kb + 3));
                float x4 = __ldcs(p + 32 * (kb + 4));
                float x5 = __ldcs(p + 32 * (kb + 5));
                float x6 = __ldcs(p + 32 * (kb + 6));
                float x7 = __ldcs(p + 32 * (kb + 7));
                a[kb + 0] = fmaf(hv, x0, a[kb + 0]);
                a[kb + 1] = fmaf(hv, x1, a[kb + 1]);
                a[kb + 2] = fmaf(hv, x2, a[kb + 2]);
                a[kb + 3] = fmaf(hv, x3, a[kb + 3]);
                a[kb + 4] = fmaf(hv, x4, a[kb + 4]);
                a[kb + 5] = fmaf(hv, x5, a[kb + 5]);
                a[kb + 6] = fmaf(hv, x6, a[kb + 6]);
                a[kb + 7] = fmaf(hv, x7, a[kb + 7]);
            }
        }
    } else {
        // tail v-tile (32 of 1600 blocks): guarded loads
        #pragma unroll 1
        for (int rr = 0; rr < 4; rr++) {
            float hv = sh[wid * 4 + rr];
            const float* p = rbase + (size_t)rr * Vn;
            #pragma unroll 4
            for (int k = 0; k < 32; k++)
                if (v0 + lane + 32 * k < Vn)
                    a[k] = fmaf(hv, __ldcs(p + 32 * k), a[k]);
        }
    }

    #pragma unroll
    for (int k = 0; k < 32; k++)
        red[wid][lane + 32 * k] = a[k];
    __syncthreads();

    // 256 threads x 4 cols: reduce 8 warps, store partial strip
    #pragma unroll
    for (int j = 0; j < 4; j++) {
        int c = tid + 256 * j;
        float s = 0.f;
        #pragma unroll
        for (int w = 0; w < 8; w++) s += red[w][c];
        int v = v0 + c;
        if (v < Vn) g_part[(size_t)blockIdx.y * Vn + v] = s;
    }
    __syncthreads();

    // last-arrival fusion: the NC-th block for this v-tile finishes the
    // softmax numerator (deterministic fixed-order sum of the partials),
    // writes the per-tile exp sum, and resets the counter for the next replay.
    if (tid == 0) {
        __threadfence();
        slast = (atomicAdd(&g_cnt[blockIdx.x], 1) == NC - 1);
    }
    __syncthreads();
    if (slast) {
        __threadfence();   // acquire: order g_part reads after counter observe
        float esum = 0.f;
        #pragma unroll
        for (int j = 0; j < 4; j++) {
            int v = v0 + tid + 256 * j;
            if (v < Vn) {
                float l = 0.f;
                #pragma unroll 8
                for (int c = 0; c < NC; c++) l += g_part[(size_t)c * Vn + v];
                float e = expf(l);     // |logit| small; max-subtraction unnecessary
                g_exp[v] = e;
                esum += e;
            }
        }
        #pragma unroll
        for (int o = 16; o; o >>= 1)
            esum += __shfl_down_sync(0xffffffffu, esum, o);
        if (lane == 0) swsum[wid] = esum;
        __syncthreads();
        if (tid == 0) {
            float s = 0.f;
            #pragma unroll
            for (int w = 0; w < 8; w++) s += swsum[w];
            g_tsum[blockIdx.x] = s;
            g_cnt[blockIdx.x] = 0;     // replay invariant
        }
    }
}

// Normalize: denominator computed by warp 0 in parallel (2 loads/lane + warp
// reduce). ~4.9us is this kernel's harness floor; leave it alone.
__global__ void k_norm(float* __restrict__ out) {
    __shared__ float sden;
    int tid = threadIdx.x;
    if (tid < 32) {
        float s = (tid < NT) ? g_tsum[tid] : 0.f;
        if (tid + 32 < NT) s += g_tsum[tid + 32];
        #pragma unroll
        for (int o = 16; o; o >>= 1)
            s += __shfl_down_sync(0xffffffffu, s, o);
        if (tid == 0) sden = 1.f / s;
    }
    __syncthreads();
    int v = blockIdx.x * blockDim.x + tid;
    if (v < Vn) out[v] = g_exp[v] * sden;
}

extern "C" void kernel_launch(void* const* d_in, const int* in_sizes, int n_in,
                              void* d_out, int out_size) {
    const float* sen  = (const float*)d_in[0];
    const float* hid  = (const float*)d_in[1];
    const float* dout = (const float*)d_in[2];
    GateParams gp;
    for (int g = 0; g < 4; g++) {
        gp.Wi[g] = (const float*)d_in[3 + 4 * g];
        gp.Wh[g] = (const float*)d_in[4 + 4 * g];
        gp.bi[g] = (const float*)d_in[5 + 4 * g];
        gp.bh[g] = (const float*)d_in[6 + 4 * g];
    }
    const float* curh = (const float*)d_in[19];
    const float* curc = (const float*)d_in[20];
    const int*   pos  = (const int*)d_in[21];
    float* out = (float*)d_out;

    k_colsum<<<Tn / 16, 256>>>(hid);
    k_gates<<<Hn / 2, 256>>>(gp, sen, curh, curc, pos);
    k_logits<<<dim3(NT, NC), 256>>>(dout);
    k_norm<<<(Vn + 255) / 256, 256>>>(out);
}